// round 17
// baseline (speedup 1.0000x reference)
#include <cuda_runtime.h>
#include <cuda_fp16.h>
#include <mma.h>
#include <cstdint>

#define NN 16384
#define DF 256
#define MT 128          // rows per CTA
#define BK 64           // K chunk
#define NCH (NN / BK)   // 256 chunks

// smem map (bytes)
#define SM_DEG  0                        // 128 ints (512 B)
#define SM_BIAS 512                      // 256 floats (1024 B)
#define SM_A    1536                     // 2 x (128 x 72 halves) = 36864 B
#define ABUF_B  18432
#define SM_B    (1536 + 36864)           // 2 x (64 x 264 halves) = 67584 B
#define BBUF_B  33792
#define ASTR    72                       // A row stride (halves)
#define BSTR    264                      // B row stride (halves)
#define SMEM_TOTAL (SM_B + 2 * BBUF_B)   // 105984

__device__ __half g_xh[(size_t)NN * DF];    // x fp16 row-major
__device__ __half g_Wh[DF * DF];            // W fp16 row-major [out][in]

// ---------------- merged prep: x -> fp16, W -> fp16 ----------------
#define XBLKS 4096
__global__ void k_prep(const float* __restrict__ x, const float* __restrict__ W) {
    if (blockIdx.x < XBLKS) {
        const size_t i = (size_t)blockIdx.x * 256 + threadIdx.x;
        const float4 v = ((const float4*)x)[i];
        __half2* d = (__half2*)(g_xh + i * 4);
        d[0] = __floats2half2_rn(v.x, v.y);
        d[1] = __floats2half2_rn(v.z, v.w);
    } else {
        const int i = (blockIdx.x - XBLKS) * 256 + threadIdx.x;
        g_Wh[i] = __float2half(W[i]);
    }
}

// ---------------- mma helpers ----------------
__device__ __forceinline__ void ldmA(uint32_t* r, uint32_t addr) {
    asm volatile("ldmatrix.sync.aligned.m8n8.x4.shared.b16 {%0,%1,%2,%3}, [%4];"
                 : "=r"(r[0]), "=r"(r[1]), "=r"(r[2]), "=r"(r[3]) : "r"(addr));
}
__device__ __forceinline__ void ldmBT(uint32_t* r, uint32_t addr) {
    asm volatile("ldmatrix.sync.aligned.m8n8.x4.trans.shared.b16 {%0,%1,%2,%3}, [%4];"
                 : "=r"(r[0]), "=r"(r[1]), "=r"(r[2]), "=r"(r[3]) : "r"(addr));
}
__device__ __forceinline__ void mma16816(float* c, const uint32_t* a, const uint32_t* b) {
    asm volatile(
        "mma.sync.aligned.m16n8k16.row.col.f32.f16.f16.f32 "
        "{%0,%1,%2,%3}, {%4,%5,%6,%7}, {%8,%9}, {%0,%1,%2,%3};"
        : "+f"(c[0]), "+f"(c[1]), "+f"(c[2]), "+f"(c[3])
        : "r"(a[0]), "r"(a[1]), "r"(a[2]), "r"(a[3]), "r"(b[0]), "r"(b[1]));
}

// ---------------- fused main: out = ((A_tile @ x)/deg) @ W^T + b ----------------
__global__ void __launch_bounds__(512)
k_main(const int* __restrict__ adj, const float* __restrict__ bias,
       float* __restrict__ out) {
    using namespace nvcuda;
    extern __shared__ char smem[];
    int* degs = (int*)(smem + SM_DEG);
    float* biasS = (float*)(smem + SM_BIAS);

    const int tid = threadIdx.x;
    const int w = tid >> 5, lid = tid & 31;
    const int blk = blockIdx.x;

    if (tid < 128) degs[tid] = 0;
    if (tid < 256) biasS[tid] = bias[tid];

    // A loader mapping: per chunk, thread handles 4 int4 (rows r0+32i, int4-col c4)
    const int r0 = tid >> 4, c4 = tid & 15;
    const int4* arow[4];
    int degl[4] = {0, 0, 0, 0};
#pragma unroll
    for (int i = 0; i < 4; ++i)
        arow[i] = (const int4*)(adj + (size_t)(blk * MT + r0 + 32 * i) * NN) + c4;

    // B loader mapping: 4 x 16B per chunk
    const int brow0 = tid >> 5, bcol = tid & 31;

    // warp tile: 32 rows x 64 cols  (wm 0..3, wn 0..3)
    const int wm = w >> 2, wn = w & 3;

    // accumulators: [tm][tn][n8 blk][4]  — mma m16n8 layout:
    //   c0,c1 -> row lid/4,   cols (lid%4)*2 + {0,1}
    //   c2,c3 -> row lid/4+8, same cols
    float acc[2][4][2][4];
#pragma unroll
    for (int tm = 0; tm < 2; ++tm)
#pragma unroll
        for (int tn = 0; tn < 4; ++tn)
#pragma unroll
            for (int b2 = 0; b2 < 2; ++b2)
#pragma unroll
                for (int e = 0; e < 4; ++e) acc[tm][tn][b2][e] = 0.0f;

    const uint32_t ab0 = (uint32_t)__cvta_generic_to_shared(smem + SM_A);
    const uint32_t bb0 = (uint32_t)__cvta_generic_to_shared(smem + SM_B);

    // ldmatrix lane-address components
    // A (x4, non-trans): addr = base + (m0 + lid%16)*ASTR*2 + (kk*16 + (lid/16)*8)*2
    // B (x4, trans):     addr = base + (kk*16 + lid%16)*BSTR*2 + (wn*64 + tn*16 + (lid/16)*8)*2
    const uint32_t aoffL = (uint32_t)((wm * 32 + (lid & 15)) * ASTR + (lid >> 4) * 8) * 2;
    const uint32_t boffL = (uint32_t)((lid & 15) * BSTR + wn * 64 + (lid >> 4) * 8) * 2;

    // prologue: B[0] cp.async, A[0] -> regs
#pragma unroll
    for (int i = 0; i < 4; ++i) {
        const int row = brow0 + 16 * i;
        const __half* src = g_xh + (size_t)row * DF + bcol * 8;
        asm volatile("cp.async.cg.shared.global [%0], [%1], 16;"
                     :: "r"(bb0 + row * (BSTR * 2) + bcol * 16), "l"(src) : "memory");
    }
    asm volatile("cp.async.commit_group;" ::: "memory");
    int4 av[4];
#pragma unroll
    for (int i = 0; i < 4; ++i) av[i] = arow[i][0];

    for (int c = 0; c < NCH; ++c) {
        // 1) store A[c] (regs -> Abuf[c&1]), fused degree accumulation
        const uint32_t ab = ab0 + (c & 1) * ABUF_B;
#pragma unroll
        for (int i = 0; i < 4; ++i) {
            const int4 v = av[i];
            degl[i] += v.x + v.y + v.z + v.w;
            const uint32_t u0 = (uint32_t)v.x * 0x3C00u + (uint32_t)v.y * 0x3C000000u;
            const uint32_t u1 = (uint32_t)v.z * 0x3C00u + (uint32_t)v.w * 0x3C000000u;
            asm volatile("st.shared.v2.b32 [%0], {%1, %2};"
                         :: "r"(ab + (r0 + 32 * i) * (ASTR * 2) + c4 * 8),
                            "r"(u0), "r"(u1));
        }
        // 2) B[c] landed
        asm volatile("cp.async.wait_group 0;" ::: "memory");
        // 3) single barrier per chunk
        __syncthreads();

        // 4) prefetch chunk c+1: B cp.async into Bbuf[(c+1)&1], A -> regs
        if (c + 1 < NCH) {
            const int k0n = (c + 1) * BK;
            const uint32_t bb = bb0 + ((c + 1) & 1) * BBUF_B;
#pragma unroll
            for (int i = 0; i < 4; ++i) {
                const int row = brow0 + 16 * i;
                const __half* src = g_xh + (size_t)(k0n + row) * DF + bcol * 8;
                asm volatile("cp.async.cg.shared.global [%0], [%1], 16;"
                             :: "r"(bb + row * (BSTR * 2) + bcol * 16), "l"(src)
                             : "memory");
            }
            asm volatile("cp.async.commit_group;" ::: "memory");
#pragma unroll
            for (int i = 0; i < 4; ++i) av[i] = arow[i][(c + 1) * 16];
        }

        // 5) compute chunk c with kk-pipelined mma.sync
        const uint32_t aB = ab0 + (c & 1) * ABUF_B + aoffL;
        const uint32_t bB = bb0 + (c & 1) * BBUF_B + boffL;

        uint32_t afr[2][4];          // [tm][4], loaded per kk
        uint32_t bfr[2][4][4];       // [buf][tn][4], double-buffered across kk

        // preload B fragments for kk=0
#pragma unroll
        for (int tn = 0; tn < 4; ++tn) ldmBT(bfr[0][tn], bB + tn * 32);

#pragma unroll
        for (int kk = 0; kk < 4; ++kk) {
            const int cur = kk & 1, nxt = cur ^ 1;
            // A fragments for this kk (arrive before MMA chain hits them)
            ldmA(afr[0], aB + kk * 32);
            ldmA(afr[1], aB + 16 * (ASTR * 2) + kk * 32);
            // B fragments for kk+1 (overlap with this kk's MMAs)
            if (kk < 3) {
                const uint32_t bk = bB + (kk + 1) * 16 * (BSTR * 2);
#pragma unroll
                for (int tn = 0; tn < 4; ++tn) ldmBT(bfr[nxt][tn], bk + tn * 32);
            }
#pragma unroll
            for (int tn = 0; tn < 4; ++tn) {
#pragma unroll
                for (int tm = 0; tm < 2; ++tm) {
                    mma16816(acc[tm][tn][0], afr[tm], &bfr[cur][tn][0]);
                    mma16816(acc[tm][tn][1], afr[tm], &bfr[cur][tn][2]);
                }
            }
        }
    }

    // degree reduction
    __syncthreads();
#pragma unroll
    for (int i = 0; i < 4; ++i) atomicAdd(&degs[r0 + 32 * i], degl[i]);
    __syncthreads();

    // ---- epilogue 1: scale by 1/deg, fp16 agg -> smem (direct from mma layout) ----
    __half* aggS = (__half*)(smem + SM_B);              // 128 x 256, stride BSTR
    {
        const int qr = lid >> 2;          // 0..7
        const int qc = (lid & 3) * 2;     // 0,2,4,6
#pragma unroll
        for (int tm = 0; tm < 2; ++tm) {
            const int row0 = wm * 32 + tm * 16 + qr;
            const int row1 = row0 + 8;
            const float inv0 = 1.0f / (float)degs[row0];
            const float inv1 = 1.0f / (float)degs[row1];
#pragma unroll
            for (int tn = 0; tn < 4; ++tn) {
#pragma unroll
                for (int b2 = 0; b2 < 2; ++b2) {
                    const int col = wn * 64 + tn * 16 + b2 * 8 + qc;
                    const float* cc = acc[tm][tn][b2];
                    *(__half2*)(aggS + (size_t)row0 * BSTR + col) =
                        __floats2half2_rn(cc[0] * inv0, cc[1] * inv0);
                    *(__half2*)(aggS + (size_t)row1 * BSTR + col) =
                        __floats2half2_rn(cc[2] * inv1, cc[3] * inv1);
                }
            }
        }
    }
    __syncthreads();

    // ---- stage 2: out_tile = aggS @ W^T + b  (W streamed from L2, wmma) ----
    wmma::fragment<wmma::accumulator, 16, 16, 16, float> acc2[2][4];
#pragma unroll
    for (int tm = 0; tm < 2; ++tm)
#pragma unroll
        for (int tn = 0; tn < 4; ++tn) wmma::fill_fragment(acc2[tm][tn], 0.0f);

#pragma unroll 4
    for (int k16 = 0; k16 < 16; ++k16) {
        wmma::fragment<wmma::matrix_a, 16, 16, 16, half, wmma::row_major> a0, a1;
        wmma::load_matrix_sync(a0, aggS + (wm * 32 + 0) * BSTR + k16 * 16, BSTR);
        wmma::load_matrix_sync(a1, aggS + (wm * 32 + 16) * BSTR + k16 * 16, BSTR);
#pragma unroll
        for (int tn = 0; tn < 4; ++tn) {
            wmma::fragment<wmma::matrix_b, 16, 16, 16, half, wmma::col_major> b;
            wmma::load_matrix_sync(b, g_Wh + (size_t)(wn * 64 + tn * 16) * DF + k16 * 16, DF);
            wmma::mma_sync(acc2[0][tn], a0, b, acc2[0][tn]);
            wmma::mma_sync(acc2[1][tn], a1, b, acc2[1][tn]);
        }
    }

    // ---- epilogue 2: + bias, store f32 coalesced (wmma scratch path) ----
    float* scratch = (float*)(smem + SM_A) + w * 256;
#pragma unroll
    for (int tm = 0; tm < 2; ++tm) {
#pragma unroll
        for (int tn = 0; tn < 4; ++tn) {
            wmma::store_matrix_sync(scratch, acc2[tm][tn], 16, wmma::mem_row_major);
            __syncwarp();
            const int r = lid >> 1, c0 = (lid & 1) * 8;
            const int grow = blk * MT + wm * 32 + tm * 16 + r;
            const int gcol = wn * 64 + tn * 16 + c0;
            const float* s = scratch + r * 16 + c0;
            float4 o0, o1;
            o0.x = s[0] + biasS[gcol + 0];  o0.y = s[1] + biasS[gcol + 1];
            o0.z = s[2] + biasS[gcol + 2];  o0.w = s[3] + biasS[gcol + 3];
            o1.x = s[4] + biasS[gcol + 4];  o1.y = s[5] + biasS[gcol + 5];
            o1.z = s[6] + biasS[gcol + 6];  o1.w = s[7] + biasS[gcol + 7];
            float4* dst = (float4*)(out + (size_t)grow * DF + gcol);
            dst[0] = o0;
            dst[1] = o1;
            __syncwarp();
        }
    }
}

extern "C" void kernel_launch(void* const* d_in, const int* in_sizes, int n_in,
                              void* d_out, int out_size) {
    const float* x    = (const float*)d_in[0];
    const int*   adj  = (const int*)d_in[1];
    const float* W    = (const float*)d_in[2];
    const float* bias = (const float*)d_in[3];
    float* out = (float*)d_out;

    cudaFuncSetAttribute((const void*)k_main,
                         cudaFuncAttributeMaxDynamicSharedMemorySize, SMEM_TOTAL);

    k_prep<<<XBLKS + DF * DF / 256, 256>>>(x, W);
    k_main<<<NN / MT, 512, SMEM_TOTAL>>>(adj, bias, out);
}